// round 9
// baseline (speedup 1.0000x reference)
#include <cuda_runtime.h>
#include <cstdint>

#define E_ACT 4
#define T_TOK 4096
#define D_DIM 1024
#define H_DIM 5632
#define CAP   4096
#define BK    16

// ---------------- scratch (static device globals; no allocation) ----------------
__device__ int   g_counts[E_ACT];
__device__ int   g_tok[E_ACT * CAP];
__device__ float g_wgt[E_ACT * CAP];
__device__ int   g_rows[T_TOK * 2];
__device__ float g_h[(size_t)E_ACT * CAP * H_DIM];   // SwiGLU activations (tf32-rounded)
__device__ float g_y[(size_t)E_ACT * CAP * D_DIM];   // per-(token,expert) scaled outputs
// tf32-pre-rounded operand copies (hoists cvt out of GEMM inner loops)
__device__ float g_xc[(size_t)T_TOK * D_DIM];
__device__ float g_w1c[(size_t)E_ACT * D_DIM * H_DIM];
__device__ float g_w3c[(size_t)E_ACT * D_DIM * H_DIM];
__device__ float g_w2c[(size_t)E_ACT * H_DIM * D_DIM];

// ---------------- helpers ----------------
__device__ __forceinline__ uint32_t f2tf(float f) {
    uint32_t r;
    asm("cvt.rna.tf32.f32 %0, %1;" : "=r"(r) : "f"(f));
    return r;
}

__device__ __forceinline__ void mma_tf32(float c[4], const uint32_t a[4], const uint32_t b[2]) {
    asm volatile(
        "mma.sync.aligned.m16n8k8.row.col.f32.tf32.tf32.f32 "
        "{%0,%1,%2,%3}, {%4,%5,%6,%7}, {%8,%9}, {%0,%1,%2,%3};\n"
        : "+f"(c[0]), "+f"(c[1]), "+f"(c[2]), "+f"(c[3])
        : "r"(a[0]), "r"(a[1]), "r"(a[2]), "r"(a[3]), "r"(b[0]), "r"(b[1]));
}

__device__ __forceinline__ void cp_async16(void* smem, const void* gmem) {
    uint32_t s = (uint32_t)__cvta_generic_to_shared(smem);
    asm volatile("cp.async.cg.shared.global [%0], [%1], 16;\n" :: "r"(s), "l"(gmem));
}
__device__ __forceinline__ void cp_commit() { asm volatile("cp.async.commit_group;\n"); }
template <int N>
__device__ __forceinline__ void cp_wait() { asm volatile("cp.async.wait_group %0;\n" :: "n"(N)); }

// ---------------- kernel 0: reset routing counters ----------------
__global__ void zero_counts_kernel() {
    if (threadIdx.x < E_ACT) g_counts[threadIdx.x] = 0;
}

// ---------------- kernel P: pre-round operands to tf32 (float4 grid-stride) ----------------
__global__ __launch_bounds__(256) void cvt_kernel(float* __restrict__ dst,
                                                  const float* __restrict__ src,
                                                  long n4) {
    long i = (long)blockIdx.x * blockDim.x + threadIdx.x;
    long stride = (long)gridDim.x * blockDim.x;
    for (; i < n4; i += stride) {
        float4 v = *(const float4*)(src + i * 4);
        v.x = __uint_as_float(f2tf(v.x));
        v.y = __uint_as_float(f2tf(v.y));
        v.z = __uint_as_float(f2tf(v.z));
        v.w = __uint_as_float(f2tf(v.w));
        *(float4*)(dst + i * 4) = v;
    }
}

// ---------------- kernel 1: gate + route (1 warp per token, full f32) ----------------
__global__ __launch_bounds__(256) void gate_kernel(const float* __restrict__ x,
                                                   const float* __restrict__ gate_w) {
    __shared__ float gws[E_ACT][D_DIM];
    int tid = threadIdx.x;
    for (int i = tid * 4; i < E_ACT * D_DIM; i += 256 * 4) {
        *(float4*)&gws[0][i] = *(const float4*)&gate_w[i];   // rows 0..3 only
    }
    __syncthreads();

    int warp = tid >> 5, lane = tid & 31;
    int t = blockIdx.x * 8 + warp;
    const float* xp = x + (size_t)t * D_DIM;

    float a0 = 0.f, a1 = 0.f, a2 = 0.f, a3 = 0.f;
    for (int i = lane; i < D_DIM; i += 32) {
        float xv = xp[i];
        a0 += xv * gws[0][i];
        a1 += xv * gws[1][i];
        a2 += xv * gws[2][i];
        a3 += xv * gws[3][i];
    }
#pragma unroll
    for (int off = 16; off; off >>= 1) {
        a0 += __shfl_xor_sync(0xffffffffu, a0, off);
        a1 += __shfl_xor_sync(0xffffffffu, a1, off);
        a2 += __shfl_xor_sync(0xffffffffu, a2, off);
        a3 += __shfl_xor_sync(0xffffffffu, a3, off);
    }

    if (lane == 0) {
        float l[4] = {a0, a1, a2, a3};
        int b0 = 0;
#pragma unroll
        for (int e2 = 1; e2 < 4; e2++) if (l[e2] > l[b0]) b0 = e2;   // stable argmax
        int b1 = (b0 == 0) ? 1 : 0;
#pragma unroll
        for (int e2 = 0; e2 < 4; e2++) if (e2 != b0 && l[e2] > l[b1]) b1 = e2;

        float wa = 1.0f / (1.0f + expf(l[b1] - l[b0]));  // renormalized top-2 softmax
        float wb = 1.0f - wa;

        int p0 = atomicAdd(&g_counts[b0], 1);
        g_tok[b0 * CAP + p0] = t;
        g_wgt[b0 * CAP + p0] = wa;
        g_rows[t * 2 + 0] = b0 * CAP + p0;

        int p1 = atomicAdd(&g_counts[b1], 1);
        g_tok[b1 * CAP + p1] = t;
        g_wgt[b1 * CAP + p1] = wb;
        g_rows[t * 2 + 1] = b1 * CAP + p1;
    }
}

// ---------------- kernel 2: grouped GEMM  h = silu(X@W1) * (X@W3) ----------------
// grid (H/64, CAP/128, E_ACT), 256 threads, 128x64 tile for BOTH w1 and w3.
// Operands pre-rounded to tf32 -> raw 32-bit LDS feeds MMA directly (no cvt).
// NOTE: no minBlocksPerMultiprocessor — forcing 3 CTAs/SM caps regs at 85 and
// spills the accumulators (the R7 regression). Natural ~92 regs, 2 CTAs/SM.
struct P1Smem {
    float Xs[3][128][20];   // pad 4: a-load banks 20g+tg -> conflict-free
    float W1[3][BK][72];    // pad to 72 (=8 mod 32): b-load banks 8tg+g -> conflict-free
    float W3[3][BK][72];
    int   toks[128];
};

__global__ __launch_bounds__(256) void pass1_kernel(const float* __restrict__ x,
                                                    const float* __restrict__ w1,
                                                    const float* __restrict__ w3) {
    extern __shared__ char smem_raw[];
    P1Smem* sm = (P1Smem*)smem_raw;

    int e = blockIdx.z;
    int Ne = g_counts[e];
    int m0 = blockIdx.y * 128;
    if (m0 >= Ne) return;
    int n0 = blockIdx.x * 64;

    int tid = threadIdx.x;
    if (tid < 128) {
        int r = m0 + tid;
        sm->toks[tid] = g_tok[e * CAP + (r < Ne ? r : 0)];
    }
    __syncthreads();

    // per-thread loader geometry (constant across stages)
    int xrow = tid >> 2;              // 0..63 (+64 for second chunk)
    int xcol = (tid & 3) * 4;         // 0,4,8,12
    const float* xg0 = x + (size_t)sm->toks[xrow] * D_DIM + xcol;
    const float* xg1 = x + (size_t)sm->toks[xrow + 64] * D_DIM + xcol;
    int wr = tid >> 4;                // 0..15
    int wc = (tid & 15) * 4;          // 0..60
    const float* w1g = w1 + ((size_t)e * D_DIM + wr) * H_DIM + n0 + wc;
    const float* w3g = w3 + ((size_t)e * D_DIM + wr) * H_DIM + n0 + wc;

    auto load_stage = [&](int s) {
        int buf = s % 3;
        int k0 = s * BK;
        cp_async16(&sm->Xs[buf][xrow][xcol],      xg0 + k0);
        cp_async16(&sm->Xs[buf][xrow + 64][xcol], xg1 + k0);
        cp_async16(&sm->W1[buf][wr][wc], w1g + (size_t)k0 * H_DIM);
        cp_async16(&sm->W3[buf][wr][wc], w3g + (size_t)k0 * H_DIM);
        cp_commit();
    };

    int warp = tid >> 5, lane = tid & 31;
    int wm = warp >> 1, wn = warp & 1;        // 4x2 warp grid: 32x32 per warp per matrix
    int g = lane >> 2, tg = lane & 3;

    float c1[2][4][4], c3[2][4][4];
#pragma unroll
    for (int mi = 0; mi < 2; mi++)
#pragma unroll
        for (int ni = 0; ni < 4; ni++)
#pragma unroll
            for (int r = 0; r < 4; r++) { c1[mi][ni][r] = 0.f; c3[mi][ni][r] = 0.f; }

    const int NK = D_DIM / BK;   // 64
    load_stage(0);
    load_stage(1);

    for (int i = 0; i < NK; i++) {
        cp_wait<1>();            // last committed group is stage i+1 -> stage i landed
        __syncthreads();         // all warps done with stage i-1's buffer
        if (i + 2 < NK) load_stage(i + 2);   // writes buf (i-1)%3: safe
        else cp_commit();                    // empty group: keeps wait<1> tail-correct

        int buf = i % 3;
#pragma unroll
        for (int k8 = 0; k8 < BK; k8 += 8) {
            uint32_t a[2][4];
#pragma unroll
            for (int mi = 0; mi < 2; mi++) {
                int rb = wm * 32 + mi * 16;
                a[mi][0] = __float_as_uint(sm->Xs[buf][rb + g][k8 + tg]);
                a[mi][1] = __float_as_uint(sm->Xs[buf][rb + g + 8][k8 + tg]);
                a[mi][2] = __float_as_uint(sm->Xs[buf][rb + g][k8 + tg + 4]);
                a[mi][3] = __float_as_uint(sm->Xs[buf][rb + g + 8][k8 + tg + 4]);
            }
#pragma unroll
            for (int ni = 0; ni < 4; ni++) {
                int col = wn * 32 + ni * 8 + g;
                uint32_t b1f[2], b3f[2];
                b1f[0] = __float_as_uint(sm->W1[buf][k8 + tg][col]);
                b1f[1] = __float_as_uint(sm->W1[buf][k8 + tg + 4][col]);
                b3f[0] = __float_as_uint(sm->W3[buf][k8 + tg][col]);
                b3f[1] = __float_as_uint(sm->W3[buf][k8 + tg + 4][col]);
#pragma unroll
                for (int mi = 0; mi < 2; mi++) {
                    mma_tf32(c1[mi][ni], a[mi], b1f);
                    mma_tf32(c3[mi][ni], a[mi], b3f);
                }
            }
        }
    }

    // epilogue: SwiGLU in f32, store tf32-rounded h (so pass2 needs no cvt)
#pragma unroll
    for (int mi = 0; mi < 2; mi++) {
#pragma unroll
        for (int hi = 0; hi < 2; hi++) {
            int row = m0 + wm * 32 + mi * 16 + g + hi * 8;
            if (row < Ne) {
                size_t base = ((size_t)e * CAP + row) * H_DIM + n0 + wn * 32;
#pragma unroll
                for (int ni = 0; ni < 4; ni++) {
                    float v1a = c1[mi][ni][hi * 2 + 0], v1b = c1[mi][ni][hi * 2 + 1];
                    float v3a = c3[mi][ni][hi * 2 + 0], v3b = c3[mi][ni][hi * 2 + 1];
                    float2 hv;
                    hv.x = __uint_as_float(f2tf((v1a / (1.f + expf(-v1a))) * v3a));
                    hv.y = __uint_as_float(f2tf((v1b / (1.f + expf(-v1b))) * v3b));
                    *(float2*)&g_h[base + ni * 8 + 2 * tg] = hv;
                }
            }
        }
    }
}

// ---------------- kernel 3: grouped GEMM  y = (h @ W2) * gate_weight ----------------
// grid (D/128, CAP/128, E_ACT), 256 threads, 128x128 tile, same 3-stage pipeline.
struct P2Smem {
    float Hs[3][128][20];
    float Ws[3][BK][136];   // 136 = 8 mod 32 -> conflict-free b loads
};

__global__ __launch_bounds__(256) void pass2_kernel(const float* __restrict__ w2) {
    extern __shared__ char smem_raw[];
    P2Smem* sm = (P2Smem*)smem_raw;

    int e = blockIdx.z;
    int Ne = g_counts[e];
    int m0 = blockIdx.y * 128;
    if (m0 >= Ne) return;
    int n0 = blockIdx.x * 128;

    int tid = threadIdx.x;
    int warp = tid >> 5, lane = tid & 31;
    int wm = warp >> 1, wn = warp & 1;        // warp tile 32x64
    int g = lane >> 2, tg = lane & 3;

    int xrow = tid >> 2;
    int xcol = (tid & 3) * 4;
    const float* hg0 = g_h + ((size_t)e * CAP + m0 + xrow) * H_DIM + xcol;
    const float* hg1 = g_h + ((size_t)e * CAP + m0 + xrow + 64) * H_DIM + xcol;
    int wr = tid >> 4;
    int wc = (tid & 15) * 4;
    const float* wg = w2 + ((size_t)e * H_DIM + wr) * D_DIM + n0 + wc;

    auto load_stage = [&](int s) {
        int buf = s % 3;
        int k0 = s * BK;
        cp_async16(&sm->Hs[buf][xrow][xcol],      hg0 + k0);
        cp_async16(&sm->Hs[buf][xrow + 64][xcol], hg1 + k0);
        cp_async16(&sm->Ws[buf][wr][wc],      wg + (size_t)k0 * D_DIM);
        cp_async16(&sm->Ws[buf][wr][wc + 64], wg + (size_t)k0 * D_DIM + 64);
        cp_commit();
    };

    float cc[2][8][4];
#pragma unroll
    for (int mi = 0; mi < 2; mi++)
#pragma unroll
        for (int ni = 0; ni < 8; ni++)
#pragma unroll
            for (int r = 0; r < 4; r++) cc[mi][ni][r] = 0.f;

    const int NK = H_DIM / BK;   // 352
    load_stage(0);
    load_stage(1);

    for (int i = 0; i < NK; i++) {
        cp_wait<1>();
        __syncthreads();
        if (i + 2 < NK) load_stage(i + 2);
        else cp_commit();                    // empty group: tail correctness

        int buf = i % 3;
#pragma unroll
        for (int k8 = 0; k8 < BK; k8 += 8) {
            uint32_t a[2][4];
#pragma unroll
            for (int mi = 0; mi < 2; mi++) {
                int rb = wm * 32 + mi * 16;
                a[mi][0] = __float_as_uint(sm->Hs[buf][rb + g][k8 + tg]);
                a[mi][1] = __float_as_uint(sm->Hs[buf][rb + g + 8][k8 + tg]);
                a[mi][2] = __float_as_uint(sm->Hs[buf][rb + g][k8 + tg + 4]);
                a[mi][3] = __float_as_uint(sm->Hs[buf][rb + g + 8][k8 + tg + 4]);
            }
#pragma unroll
            for (int ni = 0; ni < 8; ni++) {
                int col = wn * 64 + ni * 8 + g;
                uint32_t b[2];
                b[0] = __float_as_uint(sm->Ws[buf][k8 + tg][col]);
                b[1] = __float_as_uint(sm->Ws[buf][k8 + tg + 4][col]);
#pragma unroll
                for (int mi = 0; mi < 2; mi++) mma_tf32(cc[mi][ni], a[mi], b);
            }
        }
    }

#pragma unroll
    for (int mi = 0; mi < 2; mi++) {
#pragma unroll
        for (int hi = 0; hi < 2; hi++) {
            int row = m0 + wm * 32 + mi * 16 + g + hi * 8;
            if (row < Ne) {
                float wrow = g_wgt[e * CAP + row];
                size_t base = ((size_t)e * CAP + row) * D_DIM + n0 + wn * 64;
#pragma unroll
                for (int ni = 0; ni < 8; ni++) {
                    float2 v;
                    v.x = cc[mi][ni][hi * 2 + 0] * wrow;
                    v.y = cc[mi][ni][hi * 2 + 1] * wrow;
                    *(float2*)&g_y[base + ni * 8 + 2 * tg] = v;
                }
            }
        }
    }
}

// ---------------- kernel 4: deterministic combine  out[t] = y[rowA] + y[rowB] ----------------
__global__ void combine_kernel(float* __restrict__ out) {
    int idx = blockIdx.x * blockDim.x + threadIdx.x;   // float4 index, T*D/4 total
    int t = idx >> 8;                                  // 256 float4 per token row
    int c = (idx & 255) * 4;
    int rA = g_rows[t * 2 + 0];
    int rB = g_rows[t * 2 + 1];
    float4 a = *(const float4*)&g_y[(size_t)rA * D_DIM + c];
    float4 b = *(const float4*)&g_y[(size_t)rB * D_DIM + c];
    float4 o;
    o.x = a.x + b.x; o.y = a.y + b.y; o.z = a.z + b.z; o.w = a.w + b.w;
    *(float4*)&out[(size_t)t * D_DIM + c] = o;
}

// ---------------- launch ----------------
extern "C" void kernel_launch(void* const* d_in, const int* in_sizes, int n_in,
                              void* d_out, int out_size) {
    const float* x      = (const float*)d_in[0];
    const float* gate_w = (const float*)d_in[1];
    const float* w1     = (const float*)d_in[2];
    const float* w2     = (const float*)d_in[3];
    const float* w3     = (const float*)d_in[4];
    float* out = (float*)d_out;

    cudaFuncSetAttribute(pass1_kernel, cudaFuncAttributeMaxDynamicSharedMemorySize,
                         (int)sizeof(P1Smem));
    cudaFuncSetAttribute(pass2_kernel, cudaFuncAttributeMaxDynamicSharedMemorySize,
                         (int)sizeof(P2Smem));

    // device-global scratch pointers (host-side address fetch is capture-safe: no alloc)
    float *xc, *w1c, *w3c, *w2c;
    cudaGetSymbolAddress((void**)&xc,  g_xc);
    cudaGetSymbolAddress((void**)&w1c, g_w1c);
    cudaGetSymbolAddress((void**)&w3c, g_w3c);
    cudaGetSymbolAddress((void**)&w2c, g_w2c);

    const long nW = (long)E_ACT * D_DIM * H_DIM / 4;   // float4 count per weight tensor
    const long nX = (long)T_TOK * D_DIM / 4;

    zero_counts_kernel<<<1, 32>>>();
    cvt_kernel<<<4096, 256>>>(w1c, w1, nW);   // experts 0..3 = first half of [E=8,...]
    cvt_kernel<<<4096, 256>>>(w3c, w3, nW);
    cvt_kernel<<<4096, 256>>>(w2c, w2, nW);
    cvt_kernel<<<1024, 256>>>(xc, x, nX);
    gate_kernel<<<T_TOK / 8, 256>>>(x, gate_w);
    pass1_kernel<<<dim3(H_DIM / 64, CAP / 128, E_ACT), 256, sizeof(P1Smem)>>>(xc, w1c, w3c);
    pass2_kernel<<<dim3(D_DIM / 128, CAP / 128, E_ACT), 256, sizeof(P2Smem)>>>(w2c);
    combine_kernel<<<(T_TOK * D_DIM / 4) / 256, 256>>>(out);
}

// round 11
// speedup vs baseline: 1.1481x; 1.1481x over previous
#include <cuda_runtime.h>
#include <cstdint>

#define E_ACT 4
#define T_TOK 4096
#define D_DIM 1024
#define H_DIM 5632
#define CAP   4096
#define BK    16

// ---------------- scratch (static device globals; no allocation) ----------------
__device__ int   g_counts[E_ACT];
__device__ int   g_tok[E_ACT * CAP];
__device__ float g_wgt[E_ACT * CAP];
__device__ int   g_rows[T_TOK * 2];
__device__ float g_h[(size_t)E_ACT * CAP * H_DIM];   // SwiGLU activations
__device__ float g_y[(size_t)E_ACT * CAP * D_DIM];   // per-(token,expert) scaled outputs

// ---------------- helpers ----------------
__device__ __forceinline__ uint32_t f2tf(float f) {
    uint32_t r;
    asm("cvt.rna.tf32.f32 %0, %1;" : "=r"(r) : "f"(f));
    return r;
}

__device__ __forceinline__ void mma_tf32(float c[4], const uint32_t a[4], const uint32_t b[2]) {
    asm volatile(
        "mma.sync.aligned.m16n8k8.row.col.f32.tf32.tf32.f32 "
        "{%0,%1,%2,%3}, {%4,%5,%6,%7}, {%8,%9}, {%0,%1,%2,%3};\n"
        : "+f"(c[0]), "+f"(c[1]), "+f"(c[2]), "+f"(c[3])
        : "r"(a[0]), "r"(a[1]), "r"(a[2]), "r"(a[3]), "r"(b[0]), "r"(b[1]));
}

__device__ __forceinline__ void cp_async16(void* smem, const void* gmem) {
    uint32_t s = (uint32_t)__cvta_generic_to_shared(smem);
    asm volatile("cp.async.cg.shared.global [%0], [%1], 16;\n" :: "r"(s), "l"(gmem));
}
__device__ __forceinline__ void cp_commit() { asm volatile("cp.async.commit_group;\n"); }
template <int N>
__device__ __forceinline__ void cp_wait() { asm volatile("cp.async.wait_group %0;\n" :: "n"(N)); }

// ---------------- kernel 0: reset routing counters ----------------
__global__ void zero_counts_kernel() {
    if (threadIdx.x < E_ACT) g_counts[threadIdx.x] = 0;
}

// ---------------- kernel 1: gate + route (1 warp per token) ----------------
__global__ __launch_bounds__(256) void gate_kernel(const float* __restrict__ x,
                                                   const float* __restrict__ gate_w) {
    __shared__ float gws[E_ACT][D_DIM];
    int tid = threadIdx.x;
    for (int i = tid * 4; i < E_ACT * D_DIM; i += 256 * 4) {
        *(float4*)&gws[0][i] = *(const float4*)&gate_w[i];   // rows 0..3 only
    }
    __syncthreads();

    int warp = tid >> 5, lane = tid & 31;
    int t = blockIdx.x * 8 + warp;
    const float* xp = x + (size_t)t * D_DIM;

    float a0 = 0.f, a1 = 0.f, a2 = 0.f, a3 = 0.f;
    for (int i = lane; i < D_DIM; i += 32) {
        float xv = xp[i];
        a0 += xv * gws[0][i];
        a1 += xv * gws[1][i];
        a2 += xv * gws[2][i];
        a3 += xv * gws[3][i];
    }
#pragma unroll
    for (int off = 16; off; off >>= 1) {
        a0 += __shfl_xor_sync(0xffffffffu, a0, off);
        a1 += __shfl_xor_sync(0xffffffffu, a1, off);
        a2 += __shfl_xor_sync(0xffffffffu, a2, off);
        a3 += __shfl_xor_sync(0xffffffffu, a3, off);
    }

    if (lane == 0) {
        float l[4] = {a0, a1, a2, a3};
        int b0 = 0;
#pragma unroll
        for (int e2 = 1; e2 < 4; e2++) if (l[e2] > l[b0]) b0 = e2;   // stable argmax
        int b1 = (b0 == 0) ? 1 : 0;
#pragma unroll
        for (int e2 = 0; e2 < 4; e2++) if (e2 != b0 && l[e2] > l[b1]) b1 = e2;

        float wa = 1.0f / (1.0f + expf(l[b1] - l[b0]));  // renormalized top-2 softmax
        float wb = 1.0f - wa;

        int p0 = atomicAdd(&g_counts[b0], 1);
        g_tok[b0 * CAP + p0] = t;
        g_wgt[b0 * CAP + p0] = wa;
        g_rows[t * 2 + 0] = b0 * CAP + p0;

        int p1 = atomicAdd(&g_counts[b1], 1);
        g_tok[b1 * CAP + p1] = t;
        g_wgt[b1 * CAP + p1] = wb;
        g_rows[t * 2 + 1] = b1 * CAP + p1;
    }
}

// ---------------- kernel 2: grouped GEMM  h = silu(X@W1) * (X@W3) ----------------
// grid (H/64, CAP/128, E_ACT), 128 threads (4 warps, 2x2), warp tile 64x32 per matrix.
// 3-stage cp.async pipeline over BK=16 k-slices.
struct P1Smem {
    float Xs[3][128][20];   // pad 4: a-load banks 20g+tg -> conflict-free
    float W1[3][BK][72];    // 72 = 8 mod 32: b-load banks 8tg+g -> conflict-free
    float W3[3][BK][72];
    int   toks[128];
};

__global__ __launch_bounds__(128, 2) void pass1_kernel(const float* __restrict__ x,
                                                       const float* __restrict__ w1,
                                                       const float* __restrict__ w3) {
    extern __shared__ char smem_raw[];
    P1Smem* sm = (P1Smem*)smem_raw;

    int e = blockIdx.z;
    int Ne = g_counts[e];
    int m0 = blockIdx.y * 128;
    if (m0 >= Ne) return;
    int n0 = blockIdx.x * 64;

    int tid = threadIdx.x;
    {
        int r = m0 + tid;
        sm->toks[tid] = g_tok[e * CAP + (r < Ne ? r : 0)];
    }
    __syncthreads();

    // loaders: one X row per thread (4 float4), W rows split across threads
    const float* xg = x + (size_t)sm->toks[tid] * D_DIM;
    int wr = tid >> 4;                // 0..7 (+8)
    int wc = (tid & 15) * 4;          // 0..60
    const float* w1g = w1 + ((size_t)e * D_DIM + wr) * H_DIM + n0 + wc;
    const float* w3g = w3 + ((size_t)e * D_DIM + wr) * H_DIM + n0 + wc;

    auto load_stage = [&](int s) {
        int buf = s % 3;
        int k0 = s * BK;
#pragma unroll
        for (int c = 0; c < 4; c++)
            cp_async16(&sm->Xs[buf][tid][c * 4], xg + k0 + c * 4);
#pragma unroll
        for (int i = 0; i < 2; i++) {
            int kr = wr + 8 * i;
            size_t off = (size_t)(k0 + 8 * i) * H_DIM;
            cp_async16(&sm->W1[buf][kr][wc], w1g + off);
            cp_async16(&sm->W3[buf][kr][wc], w3g + off);
        }
        cp_commit();
    };

    int wid = tid >> 5, lane = tid & 31;
    int wm = wid >> 1, wn = wid & 1;          // 2x2 warps: 64x32 per warp per matrix
    int g = lane >> 2, tg = lane & 3;

    float c1[4][4][4], c3[4][4][4];
#pragma unroll
    for (int mi = 0; mi < 4; mi++)
#pragma unroll
        for (int ni = 0; ni < 4; ni++)
#pragma unroll
            for (int r = 0; r < 4; r++) { c1[mi][ni][r] = 0.f; c3[mi][ni][r] = 0.f; }

    const int NK = D_DIM / BK;   // 64
    load_stage(0);
    load_stage(1);

    for (int i = 0; i < NK; i++) {
        cp_wait<1>();            // stage i landed
        __syncthreads();         // all warps done with stage i-1's buffer
        if (i + 2 < NK) load_stage(i + 2);
        else cp_commit();        // empty group keeps wait<1> tail-correct

        int buf = i % 3;
#pragma unroll
        for (int k8 = 0; k8 < BK; k8 += 8) {
            uint32_t a[4][4];
#pragma unroll
            for (int mi = 0; mi < 4; mi++) {
                int rb = wm * 64 + mi * 16;
                a[mi][0] = f2tf(sm->Xs[buf][rb + g][k8 + tg]);
                a[mi][1] = f2tf(sm->Xs[buf][rb + g + 8][k8 + tg]);
                a[mi][2] = f2tf(sm->Xs[buf][rb + g][k8 + tg + 4]);
                a[mi][3] = f2tf(sm->Xs[buf][rb + g + 8][k8 + tg + 4]);
            }
#pragma unroll
            for (int ni = 0; ni < 4; ni++) {
                int col = wn * 32 + ni * 8 + g;
                uint32_t b1f[2], b3f[2];
                b1f[0] = f2tf(sm->W1[buf][k8 + tg][col]);
                b1f[1] = f2tf(sm->W1[buf][k8 + tg + 4][col]);
                b3f[0] = f2tf(sm->W3[buf][k8 + tg][col]);
                b3f[1] = f2tf(sm->W3[buf][k8 + tg + 4][col]);
#pragma unroll
                for (int mi = 0; mi < 4; mi++) {
                    mma_tf32(c1[mi][ni], a[mi], b1f);
                    mma_tf32(c3[mi][ni], a[mi], b3f);
                }
            }
        }
    }

    // epilogue: SwiGLU, write fp32 h
#pragma unroll
    for (int mi = 0; mi < 4; mi++) {
#pragma unroll
        for (int hi = 0; hi < 2; hi++) {
            int row = m0 + wm * 64 + mi * 16 + g + hi * 8;
            if (row < Ne) {
                size_t base = ((size_t)e * CAP + row) * H_DIM + n0 + wn * 32;
#pragma unroll
                for (int ni = 0; ni < 4; ni++) {
                    float v1a = c1[mi][ni][hi * 2 + 0], v1b = c1[mi][ni][hi * 2 + 1];
                    float v3a = c3[mi][ni][hi * 2 + 0], v3b = c3[mi][ni][hi * 2 + 1];
                    float2 hv;
                    hv.x = (v1a / (1.f + expf(-v1a))) * v3a;
                    hv.y = (v1b / (1.f + expf(-v1b))) * v3b;
                    *(float2*)&g_h[base + ni * 8 + 2 * tg] = hv;
                }
            }
        }
    }
}

// ---------------- kernel 3: grouped GEMM  y = (h @ W2) * gate_weight ----------------
// grid (D/128, CAP/128, E_ACT), 128 threads (4 warps, 2x2), warp tile 64x64.
struct P2Smem {
    float Hs[3][128][20];
    float Ws[3][BK][136];   // 136 = 8 mod 32 -> conflict-free b loads
};

__global__ __launch_bounds__(128, 2) void pass2_kernel(const float* __restrict__ w2) {
    extern __shared__ char smem_raw[];
    P2Smem* sm = (P2Smem*)smem_raw;

    int e = blockIdx.z;
    int Ne = g_counts[e];
    int m0 = blockIdx.y * 128;
    if (m0 >= Ne) return;
    int n0 = blockIdx.x * 128;

    int tid = threadIdx.x;
    int wid = tid >> 5, lane = tid & 31;
    int wm = wid >> 1, wn = wid & 1;          // 2x2 warps: 64x64 per warp
    int g = lane >> 2, tg = lane & 3;

    const float* hg = g_h + ((size_t)e * CAP + m0 + tid) * H_DIM;
    int wr = tid >> 5;                 // 0..3 (+4i)
    int wc = (tid & 31) * 4;           // 0..124
    const float* wg = w2 + ((size_t)e * H_DIM + wr) * D_DIM + n0 + wc;

    auto load_stage = [&](int s) {
        int buf = s % 3;
        int k0 = s * BK;
#pragma unroll
        for (int c = 0; c < 4; c++)
            cp_async16(&sm->Hs[buf][tid][c * 4], hg + k0 + c * 4);
#pragma unroll
        for (int i = 0; i < 4; i++) {
            int kr = wr + 4 * i;
            cp_async16(&sm->Ws[buf][kr][wc], wg + (size_t)(k0 + 4 * i) * D_DIM);
        }
        cp_commit();
    };

    float cc[4][8][4];
#pragma unroll
    for (int mi = 0; mi < 4; mi++)
#pragma unroll
        for (int ni = 0; ni < 8; ni++)
#pragma unroll
            for (int r = 0; r < 4; r++) cc[mi][ni][r] = 0.f;

    const int NK = H_DIM / BK;   // 352
    load_stage(0);
    load_stage(1);

    for (int i = 0; i < NK; i++) {
        cp_wait<1>();
        __syncthreads();
        if (i + 2 < NK) load_stage(i + 2);
        else cp_commit();

        int buf = i % 3;
#pragma unroll
        for (int k8 = 0; k8 < BK; k8 += 8) {
            uint32_t a[4][4];
#pragma unroll
            for (int mi = 0; mi < 4; mi++) {
                int rb = wm * 64 + mi * 16;
                a[mi][0] = f2tf(sm->Hs[buf][rb + g][k8 + tg]);
                a[mi][1] = f2tf(sm->Hs[buf][rb + g + 8][k8 + tg]);
                a[mi][2] = f2tf(sm->Hs[buf][rb + g][k8 + tg + 4]);
                a[mi][3] = f2tf(sm->Hs[buf][rb + g + 8][k8 + tg + 4]);
            }
#pragma unroll
            for (int ni = 0; ni < 8; ni++) {
                int col = wn * 64 + ni * 8 + g;
                uint32_t b[2];
                b[0] = f2tf(sm->Ws[buf][k8 + tg][col]);
                b[1] = f2tf(sm->Ws[buf][k8 + tg + 4][col]);
#pragma unroll
                for (int mi = 0; mi < 4; mi++) mma_tf32(cc[mi][ni], a[mi], b);
            }
        }
    }

#pragma unroll
    for (int mi = 0; mi < 4; mi++) {
#pragma unroll
        for (int hi = 0; hi < 2; hi++) {
            int row = m0 + wm * 64 + mi * 16 + g + hi * 8;
            if (row < Ne) {
                float wrow = g_wgt[e * CAP + row];
                size_t base = ((size_t)e * CAP + row) * D_DIM + n0 + wn * 64;
#pragma unroll
                for (int ni = 0; ni < 8; ni++) {
                    float2 v;
                    v.x = cc[mi][ni][hi * 2 + 0] * wrow;
                    v.y = cc[mi][ni][hi * 2 + 1] * wrow;
                    *(float2*)&g_y[base + ni * 8 + 2 * tg] = v;
                }
            }
        }
    }
}

// ---------------- kernel 4: deterministic combine  out[t] = y[rowA] + y[rowB] ----------------
__global__ void combine_kernel(float* __restrict__ out) {
    int idx = blockIdx.x * blockDim.x + threadIdx.x;   // float4 index, T*D/4 total
    int t = idx >> 8;                                  // 256 float4 per token row
    int c = (idx & 255) * 4;
    int rA = g_rows[t * 2 + 0];
    int rB = g_rows[t * 2 + 1];
    float4 a = *(const float4*)&g_y[(size_t)rA * D_DIM + c];
    float4 b = *(const float4*)&g_y[(size_t)rB * D_DIM + c];
    float4 o;
    o.x = a.x + b.x; o.y = a.y + b.y; o.z = a.z + b.z; o.w = a.w + b.w;
    *(float4*)&out[(size_t)t * D_DIM + c] = o;
}

// ---------------- launch ----------------
extern "C" void kernel_launch(void* const* d_in, const int* in_sizes, int n_in,
                              void* d_out, int out_size) {
    const float* x      = (const float*)d_in[0];
    const float* gate_w = (const float*)d_in[1];
    const float* w1     = (const float*)d_in[2];
    const float* w2     = (const float*)d_in[3];
    const float* w3     = (const float*)d_in[4];
    float* out = (float*)d_out;

    cudaFuncSetAttribute(pass1_kernel, cudaFuncAttributeMaxDynamicSharedMemorySize,
                         (int)sizeof(P1Smem));
    cudaFuncSetAttribute(pass2_kernel, cudaFuncAttributeMaxDynamicSharedMemorySize,
                         (int)sizeof(P2Smem));

    zero_counts_kernel<<<1, 32>>>();
    gate_kernel<<<T_TOK / 8, 256>>>(x, gate_w);
    pass1_kernel<<<dim3(H_DIM / 64, CAP / 128, E_ACT), 128, sizeof(P1Smem)>>>(x, w1, w3);
    pass2_kernel<<<dim3(D_DIM / 128, CAP / 128, E_ACT), 128, sizeof(P2Smem)>>>(w2);
    combine_kernel<<<(T_TOK * D_DIM / 4) / 256, 256>>>(out);
}

// round 12
// speedup vs baseline: 1.4041x; 1.2231x over previous
#include <cuda_runtime.h>
#include <cstdint>

#define E_ACT 4
#define T_TOK 4096
#define D_DIM 1024
#define H_DIM 5632
#define CAP   4096
#define BK    32

// ---------------- scratch (static device globals; no allocation) ----------------
__device__ int   g_counts[E_ACT];
__device__ int   g_tok[E_ACT * CAP];
__device__ float g_wgt[E_ACT * CAP];
__device__ int   g_rows[T_TOK * 2];
__device__ float g_h[(size_t)E_ACT * CAP * H_DIM];   // SwiGLU activations
__device__ float g_y[(size_t)E_ACT * CAP * D_DIM];   // per-(token,expert) scaled outputs

// ---------------- helpers ----------------
__device__ __forceinline__ uint32_t f2tf(float f) {
    uint32_t r;
    asm("cvt.rna.tf32.f32 %0, %1;" : "=r"(r) : "f"(f));
    return r;
}

__device__ __forceinline__ void mma_tf32(float c[4], const uint32_t a[4], const uint32_t b[2]) {
    asm volatile(
        "mma.sync.aligned.m16n8k8.row.col.f32.tf32.tf32.f32 "
        "{%0,%1,%2,%3}, {%4,%5,%6,%7}, {%8,%9}, {%0,%1,%2,%3};\n"
        : "+f"(c[0]), "+f"(c[1]), "+f"(c[2]), "+f"(c[3])
        : "r"(a[0]), "r"(a[1]), "r"(a[2]), "r"(a[3]), "r"(b[0]), "r"(b[1]));
}

__device__ __forceinline__ void cp_async16(void* smem, const void* gmem) {
    uint32_t s = (uint32_t)__cvta_generic_to_shared(smem);
    asm volatile("cp.async.cg.shared.global [%0], [%1], 16;\n" :: "r"(s), "l"(gmem));
}
__device__ __forceinline__ void cp_commit() { asm volatile("cp.async.commit_group;\n"); }
template <int N>
__device__ __forceinline__ void cp_wait() { asm volatile("cp.async.wait_group %0;\n" :: "n"(N)); }

// ---------------- kernel 0: reset routing counters ----------------
__global__ void zero_counts_kernel() {
    if (threadIdx.x < E_ACT) g_counts[threadIdx.x] = 0;
}

// ---------------- kernel 1: gate + route (1 warp per token) ----------------
__global__ __launch_bounds__(256) void gate_kernel(const float* __restrict__ x,
                                                   const float* __restrict__ gate_w) {
    __shared__ float gws[E_ACT][D_DIM];
    int tid = threadIdx.x;
    for (int i = tid * 4; i < E_ACT * D_DIM; i += 256 * 4) {
        *(float4*)&gws[0][i] = *(const float4*)&gate_w[i];   // rows 0..3 only
    }
    __syncthreads();

    int warp = tid >> 5, lane = tid & 31;
    int t = blockIdx.x * 8 + warp;
    const float* xp = x + (size_t)t * D_DIM;

    float a0 = 0.f, a1 = 0.f, a2 = 0.f, a3 = 0.f;
    for (int i = lane; i < D_DIM; i += 32) {
        float xv = xp[i];
        a0 += xv * gws[0][i];
        a1 += xv * gws[1][i];
        a2 += xv * gws[2][i];
        a3 += xv * gws[3][i];
    }
#pragma unroll
    for (int off = 16; off; off >>= 1) {
        a0 += __shfl_xor_sync(0xffffffffu, a0, off);
        a1 += __shfl_xor_sync(0xffffffffu, a1, off);
        a2 += __shfl_xor_sync(0xffffffffu, a2, off);
        a3 += __shfl_xor_sync(0xffffffffu, a3, off);
    }

    if (lane == 0) {
        float l[4] = {a0, a1, a2, a3};
        int b0 = 0;
#pragma unroll
        for (int e2 = 1; e2 < 4; e2++) if (l[e2] > l[b0]) b0 = e2;   // stable argmax
        int b1 = (b0 == 0) ? 1 : 0;
#pragma unroll
        for (int e2 = 0; e2 < 4; e2++) if (e2 != b0 && l[e2] > l[b1]) b1 = e2;

        float wa = 1.0f / (1.0f + expf(l[b1] - l[b0]));  // renormalized top-2 softmax
        float wb = 1.0f - wa;

        int p0 = atomicAdd(&g_counts[b0], 1);
        g_tok[b0 * CAP + p0] = t;
        g_wgt[b0 * CAP + p0] = wa;
        g_rows[t * 2 + 0] = b0 * CAP + p0;

        int p1 = atomicAdd(&g_counts[b1], 1);
        g_tok[b1 * CAP + p1] = t;
        g_wgt[b1 * CAP + p1] = wb;
        g_rows[t * 2 + 1] = b1 * CAP + p1;
    }
}

// ---------------- kernel 2: grouped GEMM  h = silu(X@W1) * (X@W3) ----------------
// grid (H/64, CAP/128, E_ACT), 256 threads (R6 warp layout), BK=32 k-slices,
// 3-stage cp.async pipeline (depth-2 prefetch), 4 k8-bodies per barrier.
struct P1Smem {
    float Xs[3][128][36];   // stride 36: a-load banks 4g+tg -> conflict-free
    float W1[3][BK][72];    // 72 = 8 mod 32: b-load banks 8tg+g -> conflict-free
    float W3[3][BK][72];
    int   toks[128];
};

__global__ __launch_bounds__(256) void pass1_kernel(const float* __restrict__ x,
                                                    const float* __restrict__ w1,
                                                    const float* __restrict__ w3) {
    extern __shared__ char smem_raw[];
    P1Smem* sm = (P1Smem*)smem_raw;

    int e = blockIdx.z;
    int Ne = g_counts[e];
    int m0 = blockIdx.y * 128;
    if (m0 >= Ne) return;
    int n0 = blockIdx.x * 64;

    int tid = threadIdx.x;
    if (tid < 128) {
        int r = m0 + tid;
        sm->toks[tid] = g_tok[e * CAP + (r < Ne ? r : 0)];
    }
    __syncthreads();

    // loader geometry (constant across stages)
    int xrow = tid >> 2;              // 0..63 (+64 second half)
    int xc4 = (tid & 3) * 4;          // cols {xc4, xc4+16} cover 32 floats
    const float* xg0 = x + (size_t)sm->toks[xrow] * D_DIM + xc4;
    const float* xg1 = x + (size_t)sm->toks[xrow + 64] * D_DIM + xc4;
    int wr = tid >> 4;                // 0..15 (+16 second half)
    int wc = (tid & 15) * 4;          // 0..60
    const float* w1g = w1 + ((size_t)e * D_DIM + wr) * H_DIM + n0 + wc;
    const float* w3g = w3 + ((size_t)e * D_DIM + wr) * H_DIM + n0 + wc;

    auto load_stage = [&](int s) {
        int buf = s % 3;
        int k0 = s * BK;
        cp_async16(&sm->Xs[buf][xrow][xc4],           xg0 + k0);
        cp_async16(&sm->Xs[buf][xrow][xc4 + 16],      xg0 + k0 + 16);
        cp_async16(&sm->Xs[buf][xrow + 64][xc4],      xg1 + k0);
        cp_async16(&sm->Xs[buf][xrow + 64][xc4 + 16], xg1 + k0 + 16);
#pragma unroll
        for (int i = 0; i < 2; i++) {
            int kr = wr + 16 * i;
            size_t off = (size_t)(k0 + 16 * i) * H_DIM;
            cp_async16(&sm->W1[buf][kr][wc], w1g + off);
            cp_async16(&sm->W3[buf][kr][wc], w3g + off);
        }
        cp_commit();
    };

    int warp = tid >> 5, lane = tid & 31;
    int wm = warp >> 1, wn = warp & 1;        // 4x2 warp grid: 32x32 per warp per matrix
    int g = lane >> 2, tg = lane & 3;

    float c1[2][4][4], c3[2][4][4];
#pragma unroll
    for (int mi = 0; mi < 2; mi++)
#pragma unroll
        for (int ni = 0; ni < 4; ni++)
#pragma unroll
            for (int r = 0; r < 4; r++) { c1[mi][ni][r] = 0.f; c3[mi][ni][r] = 0.f; }

    const int NK = D_DIM / BK;   // 32
    load_stage(0);
    load_stage(1);

    for (int i = 0; i < NK; i++) {
        cp_wait<1>();            // stage i landed (invariant: 1 commit per iteration)
        __syncthreads();         // all warps done with stage i-1's buffer
        if (i + 2 < NK) load_stage(i + 2);   // writes buf (i-1)%3: safe
        else cp_commit();                    // empty group keeps wait<1> tail-correct

        int buf = i % 3;
#pragma unroll
        for (int k8 = 0; k8 < BK; k8 += 8) {
            uint32_t a[2][4];
#pragma unroll
            for (int mi = 0; mi < 2; mi++) {
                int rb = wm * 32 + mi * 16;
                a[mi][0] = f2tf(sm->Xs[buf][rb + g][k8 + tg]);
                a[mi][1] = f2tf(sm->Xs[buf][rb + g + 8][k8 + tg]);
                a[mi][2] = f2tf(sm->Xs[buf][rb + g][k8 + tg + 4]);
                a[mi][3] = f2tf(sm->Xs[buf][rb + g + 8][k8 + tg + 4]);
            }
#pragma unroll
            for (int ni = 0; ni < 4; ni++) {
                int col = wn * 32 + ni * 8 + g;
                uint32_t b1f[2], b3f[2];
                b1f[0] = f2tf(sm->W1[buf][k8 + tg][col]);
                b1f[1] = f2tf(sm->W1[buf][k8 + tg + 4][col]);
                b3f[0] = f2tf(sm->W3[buf][k8 + tg][col]);
                b3f[1] = f2tf(sm->W3[buf][k8 + tg + 4][col]);
#pragma unroll
                for (int mi = 0; mi < 2; mi++) {
                    mma_tf32(c1[mi][ni], a[mi], b1f);
                    mma_tf32(c3[mi][ni], a[mi], b3f);
                }
            }
        }
    }

    // epilogue: SwiGLU, write fp32 h
#pragma unroll
    for (int mi = 0; mi < 2; mi++) {
#pragma unroll
        for (int hi = 0; hi < 2; hi++) {
            int row = m0 + wm * 32 + mi * 16 + g + hi * 8;
            if (row < Ne) {
                size_t base = ((size_t)e * CAP + row) * H_DIM + n0 + wn * 32;
#pragma unroll
                for (int ni = 0; ni < 4; ni++) {
                    float v1a = c1[mi][ni][hi * 2 + 0], v1b = c1[mi][ni][hi * 2 + 1];
                    float v3a = c3[mi][ni][hi * 2 + 0], v3b = c3[mi][ni][hi * 2 + 1];
                    float2 hv;
                    hv.x = (v1a / (1.f + expf(-v1a))) * v3a;
                    hv.y = (v1b / (1.f + expf(-v1b))) * v3b;
                    *(float2*)&g_h[base + ni * 8 + 2 * tg] = hv;
                }
            }
        }
    }
}

// ---------------- kernel 3: grouped GEMM  y = (h @ W2) * gate_weight ----------------
// grid (D/128, CAP/128, E_ACT), 256 threads, 128x128 tile, BK=32, same pipeline.
struct P2Smem {
    float Hs[3][128][36];
    float Ws[3][BK][136];   // 136 = 8 mod 32 -> conflict-free b loads
};

__global__ __launch_bounds__(256) void pass2_kernel(const float* __restrict__ w2) {
    extern __shared__ char smem_raw[];
    P2Smem* sm = (P2Smem*)smem_raw;

    int e = blockIdx.z;
    int Ne = g_counts[e];
    int m0 = blockIdx.y * 128;
    if (m0 >= Ne) return;
    int n0 = blockIdx.x * 128;

    int tid = threadIdx.x;
    int warp = tid >> 5, lane = tid & 31;
    int wm = warp >> 1, wn = warp & 1;        // warp tile 32x64
    int g = lane >> 2, tg = lane & 3;

    int xrow = tid >> 2;
    int xc4 = (tid & 3) * 4;
    const float* hg0 = g_h + ((size_t)e * CAP + m0 + xrow) * H_DIM + xc4;
    const float* hg1 = g_h + ((size_t)e * CAP + m0 + xrow + 64) * H_DIM + xc4;
    int wr = tid >> 5;                 // 0..7 (+8i)
    int wc = (tid & 31) * 4;           // 0..124
    const float* wg = w2 + ((size_t)e * H_DIM + wr) * D_DIM + n0 + wc;

    auto load_stage = [&](int s) {
        int buf = s % 3;
        int k0 = s * BK;
        cp_async16(&sm->Hs[buf][xrow][xc4],           hg0 + k0);
        cp_async16(&sm->Hs[buf][xrow][xc4 + 16],      hg0 + k0 + 16);
        cp_async16(&sm->Hs[buf][xrow + 64][xc4],      hg1 + k0);
        cp_async16(&sm->Hs[buf][xrow + 64][xc4 + 16], hg1 + k0 + 16);
#pragma unroll
        for (int i = 0; i < 4; i++) {
            int kr = wr + 8 * i;
            cp_async16(&sm->Ws[buf][kr][wc], wg + (size_t)(k0 + 8 * i) * D_DIM);
        }
        cp_commit();
    };

    float cc[2][8][4];
#pragma unroll
    for (int mi = 0; mi < 2; mi++)
#pragma unroll
        for (int ni = 0; ni < 8; ni++)
#pragma unroll
            for (int r = 0; r < 4; r++) cc[mi][ni][r] = 0.f;

    const int NK = H_DIM / BK;   // 176
    load_stage(0);
    load_stage(1);

    for (int i = 0; i < NK; i++) {
        cp_wait<1>();
        __syncthreads();
        if (i + 2 < NK) load_stage(i + 2);
        else cp_commit();

        int buf = i % 3;
#pragma unroll
        for (int k8 = 0; k8 < BK; k8 += 8) {
            uint32_t a[2][4];
#pragma unroll
            for (int mi = 0; mi < 2; mi++) {
                int rb = wm * 32 + mi * 16;
                a[mi][0] = f2tf(sm->Hs[buf][rb + g][k8 + tg]);
                a[mi][1] = f2tf(sm->Hs[buf][rb + g + 8][k8 + tg]);
                a[mi][2] = f2tf(sm->Hs[buf][rb + g][k8 + tg + 4]);
                a[mi][3] = f2tf(sm->Hs[buf][rb + g + 8][k8 + tg + 4]);
            }
#pragma unroll
            for (int ni = 0; ni < 8; ni++) {
                int col = wn * 64 + ni * 8 + g;
                uint32_t b[2];
                b[0] = f2tf(sm->Ws[buf][k8 + tg][col]);
                b[1] = f2tf(sm->Ws[buf][k8 + tg + 4][col]);
#pragma unroll
                for (int mi = 0; mi < 2; mi++) mma_tf32(cc[mi][ni], a[mi], b);
            }
        }
    }

#pragma unroll
    for (int mi = 0; mi < 2; mi++) {
#pragma unroll
        for (int hi = 0; hi < 2; hi++) {
            int row = m0 + wm * 32 + mi * 16 + g + hi * 8;
            if (row < Ne) {
                float wrow = g_wgt[e * CAP + row];
                size_t base = ((size_t)e * CAP + row) * D_DIM + n0 + wn * 64;
#pragma unroll
                for (int ni = 0; ni < 8; ni++) {
                    float2 v;
                    v.x = cc[mi][ni][hi * 2 + 0] * wrow;
                    v.y = cc[mi][ni][hi * 2 + 1] * wrow;
                    *(float2*)&g_y[base + ni * 8 + 2 * tg] = v;
                }
            }
        }
    }
}

// ---------------- kernel 4: deterministic combine  out[t] = y[rowA] + y[rowB] ----------------
__global__ void combine_kernel(float* __restrict__ out) {
    int idx = blockIdx.x * blockDim.x + threadIdx.x;   // float4 index, T*D/4 total
    int t = idx >> 8;                                  // 256 float4 per token row
    int c = (idx & 255) * 4;
    int rA = g_rows[t * 2 + 0];
    int rB = g_rows[t * 2 + 1];
    float4 a = *(const float4*)&g_y[(size_t)rA * D_DIM + c];
    float4 b = *(const float4*)&g_y[(size_t)rB * D_DIM + c];
    float4 o;
    o.x = a.x + b.x; o.y = a.y + b.y; o.z = a.z + b.z; o.w = a.w + b.w;
    *(float4*)&out[(size_t)t * D_DIM + c] = o;
}

// ---------------- launch ----------------
extern "C" void kernel_launch(void* const* d_in, const int* in_sizes, int n_in,
                              void* d_out, int out_size) {
    const float* x      = (const float*)d_in[0];
    const float* gate_w = (const float*)d_in[1];
    const float* w1     = (const float*)d_in[2];
    const float* w2     = (const float*)d_in[3];
    const float* w3     = (const float*)d_in[4];
    float* out = (float*)d_out;

    cudaFuncSetAttribute(pass1_kernel, cudaFuncAttributeMaxDynamicSharedMemorySize,
                         (int)sizeof(P1Smem));
    cudaFuncSetAttribute(pass2_kernel, cudaFuncAttributeMaxDynamicSharedMemorySize,
                         (int)sizeof(P2Smem));

    zero_counts_kernel<<<1, 32>>>();
    gate_kernel<<<T_TOK / 8, 256>>>(x, gate_w);
    pass1_kernel<<<dim3(H_DIM / 64, CAP / 128, E_ACT), 256, sizeof(P1Smem)>>>(x, w1, w3);
    pass2_kernel<<<dim3(D_DIM / 128, CAP / 128, E_ACT), 256, sizeof(P2Smem)>>>(w2);
    combine_kernel<<<(T_TOK * D_DIM / 4) / 256, 256>>>(out);
}

// round 13
// speedup vs baseline: 1.4520x; 1.0341x over previous
#include <cuda_runtime.h>
#include <cstdint>

#define E_ACT 4
#define T_TOK 4096
#define D_DIM 1024
#define H_DIM 5632
#define CAP   4096
#define BK    32

// ---------------- scratch (static device globals; no allocation) ----------------
__device__ int   g_counts[E_ACT];
__device__ int   g_tok[E_ACT * CAP];
__device__ float g_wgt[E_ACT * CAP];
__device__ int   g_rows[T_TOK * 2];
__device__ float g_h[(size_t)E_ACT * CAP * H_DIM];   // SwiGLU activations
__device__ float g_y[(size_t)E_ACT * CAP * D_DIM];   // per-(token,expert) scaled outputs

// ---------------- helpers ----------------
__device__ __forceinline__ uint32_t f2tf(float f) {
    uint32_t r;
    asm("cvt.rna.tf32.f32 %0, %1;" : "=r"(r) : "f"(f));
    return r;
}

__device__ __forceinline__ void mma_tf32(float c[4], const uint32_t a[4], const uint32_t b[2]) {
    asm volatile(
        "mma.sync.aligned.m16n8k8.row.col.f32.tf32.tf32.f32 "
        "{%0,%1,%2,%3}, {%4,%5,%6,%7}, {%8,%9}, {%0,%1,%2,%3};\n"
        : "+f"(c[0]), "+f"(c[1]), "+f"(c[2]), "+f"(c[3])
        : "r"(a[0]), "r"(a[1]), "r"(a[2]), "r"(a[3]), "r"(b[0]), "r"(b[1]));
}

__device__ __forceinline__ void cp_async16(void* smem, const void* gmem) {
    uint32_t s = (uint32_t)__cvta_generic_to_shared(smem);
    asm volatile("cp.async.cg.shared.global [%0], [%1], 16;\n" :: "r"(s), "l"(gmem));
}
__device__ __forceinline__ void cp_commit() { asm volatile("cp.async.commit_group;\n"); }
template <int N>
__device__ __forceinline__ void cp_wait() { asm volatile("cp.async.wait_group %0;\n" :: "n"(N)); }

// ---------------- kernel 0: reset routing counters ----------------
__global__ void zero_counts_kernel() {
    if (threadIdx.x < E_ACT) g_counts[threadIdx.x] = 0;
}

// ---------------- kernel 1: gate + route (1 warp per token) ----------------
__global__ __launch_bounds__(256) void gate_kernel(const float* __restrict__ x,
                                                   const float* __restrict__ gate_w) {
    __shared__ float gws[E_ACT][D_DIM];
    int tid = threadIdx.x;
    for (int i = tid * 4; i < E_ACT * D_DIM; i += 256 * 4) {
        *(float4*)&gws[0][i] = *(const float4*)&gate_w[i];   // rows 0..3 only
    }
    __syncthreads();

    int warp = tid >> 5, lane = tid & 31;
    int t = blockIdx.x * 8 + warp;
    const float* xp = x + (size_t)t * D_DIM;

    float a0 = 0.f, a1 = 0.f, a2 = 0.f, a3 = 0.f;
    for (int i = lane; i < D_DIM; i += 32) {
        float xv = xp[i];
        a0 += xv * gws[0][i];
        a1 += xv * gws[1][i];
        a2 += xv * gws[2][i];
        a3 += xv * gws[3][i];
    }
#pragma unroll
    for (int off = 16; off; off >>= 1) {
        a0 += __shfl_xor_sync(0xffffffffu, a0, off);
        a1 += __shfl_xor_sync(0xffffffffu, a1, off);
        a2 += __shfl_xor_sync(0xffffffffu, a2, off);
        a3 += __shfl_xor_sync(0xffffffffu, a3, off);
    }

    if (lane == 0) {
        float l[4] = {a0, a1, a2, a3};
        int b0 = 0;
#pragma unroll
        for (int e2 = 1; e2 < 4; e2++) if (l[e2] > l[b0]) b0 = e2;   // stable argmax
        int b1 = (b0 == 0) ? 1 : 0;
#pragma unroll
        for (int e2 = 0; e2 < 4; e2++) if (e2 != b0 && l[e2] > l[b1]) b1 = e2;

        float wa = 1.0f / (1.0f + expf(l[b1] - l[b0]));  // renormalized top-2 softmax
        float wb = 1.0f - wa;

        int p0 = atomicAdd(&g_counts[b0], 1);
        g_tok[b0 * CAP + p0] = t;
        g_wgt[b0 * CAP + p0] = wa;
        g_rows[t * 2 + 0] = b0 * CAP + p0;

        int p1 = atomicAdd(&g_counts[b1], 1);
        g_tok[b1 * CAP + p1] = t;
        g_wgt[b1 * CAP + p1] = wb;
        g_rows[t * 2 + 1] = b1 * CAP + p1;
    }
}

// ---------------- kernel 2: grouped GEMM  h = silu(X@W1) * (X@W3) ----------------
// grid (H/64, CAP/128, E_ACT), 256 threads, BK=32 k-slices, 3-stage cp.async
// smem pipeline + k8-level fragment double-buffering (LDS hidden behind MMA).
struct P1Smem {
    float Xs[3][128][36];   // stride 36: a-load banks 4g+tg -> conflict-free
    float W1[3][BK][72];    // 72 = 8 mod 32: b-load banks 8tg+g -> conflict-free
    float W3[3][BK][72];
    int   toks[128];
};

__global__ __launch_bounds__(256, 2) void pass1_kernel(const float* __restrict__ x,
                                                       const float* __restrict__ w1,
                                                       const float* __restrict__ w3) {
    extern __shared__ char smem_raw[];
    P1Smem* sm = (P1Smem*)smem_raw;

    int e = blockIdx.z;
    int Ne = g_counts[e];
    int m0 = blockIdx.y * 128;
    if (m0 >= Ne) return;
    int n0 = blockIdx.x * 64;

    int tid = threadIdx.x;
    if (tid < 128) {
        int r = m0 + tid;
        sm->toks[tid] = g_tok[e * CAP + (r < Ne ? r : 0)];
    }
    __syncthreads();

    // gmem loader geometry (constant across stages)
    int xrow = tid >> 2;
    int xc4 = (tid & 3) * 4;
    const float* xg0 = x + (size_t)sm->toks[xrow] * D_DIM + xc4;
    const float* xg1 = x + (size_t)sm->toks[xrow + 64] * D_DIM + xc4;
    int wr = tid >> 4;
    int wc = (tid & 15) * 4;
    const float* w1g = w1 + ((size_t)e * D_DIM + wr) * H_DIM + n0 + wc;
    const float* w3g = w3 + ((size_t)e * D_DIM + wr) * H_DIM + n0 + wc;

    auto load_stage = [&](int s) {
        int buf = s % 3;
        int k0 = s * BK;
        cp_async16(&sm->Xs[buf][xrow][xc4],           xg0 + k0);
        cp_async16(&sm->Xs[buf][xrow][xc4 + 16],      xg0 + k0 + 16);
        cp_async16(&sm->Xs[buf][xrow + 64][xc4],      xg1 + k0);
        cp_async16(&sm->Xs[buf][xrow + 64][xc4 + 16], xg1 + k0 + 16);
#pragma unroll
        for (int i = 0; i < 2; i++) {
            int kr = wr + 16 * i;
            size_t off = (size_t)(k0 + 16 * i) * H_DIM;
            cp_async16(&sm->W1[buf][kr][wc], w1g + off);
            cp_async16(&sm->W3[buf][kr][wc], w3g + off);
        }
        cp_commit();
    };

    int warp = tid >> 5, lane = tid & 31;
    int wm = warp >> 1, wn = warp & 1;        // 4x2 warp grid: 32x32 per warp per matrix
    int g = lane >> 2, tg = lane & 3;

    float c1[2][4][4], c3[2][4][4];
#pragma unroll
    for (int mi = 0; mi < 2; mi++)
#pragma unroll
        for (int ni = 0; ni < 4; ni++)
#pragma unroll
            for (int r = 0; r < 4; r++) { c1[mi][ni][r] = 0.f; c3[mi][ni][r] = 0.f; }

    // double-buffered register fragments
    uint32_t a[2][2][4], b1f[2][4][2], b3f[2][4][2];
    auto loadfrag = [&](int s, int buf, int k8) {
#pragma unroll
        for (int mi = 0; mi < 2; mi++) {
            int rb = wm * 32 + mi * 16;
            a[s][mi][0] = f2tf(sm->Xs[buf][rb + g][k8 + tg]);
            a[s][mi][1] = f2tf(sm->Xs[buf][rb + g + 8][k8 + tg]);
            a[s][mi][2] = f2tf(sm->Xs[buf][rb + g][k8 + tg + 4]);
            a[s][mi][3] = f2tf(sm->Xs[buf][rb + g + 8][k8 + tg + 4]);
        }
#pragma unroll
        for (int ni = 0; ni < 4; ni++) {
            int col = wn * 32 + ni * 8 + g;
            b1f[s][ni][0] = f2tf(sm->W1[buf][k8 + tg][col]);
            b1f[s][ni][1] = f2tf(sm->W1[buf][k8 + tg + 4][col]);
            b3f[s][ni][0] = f2tf(sm->W3[buf][k8 + tg][col]);
            b3f[s][ni][1] = f2tf(sm->W3[buf][k8 + tg + 4][col]);
        }
    };

    const int NK = D_DIM / BK;   // 32
    load_stage(0);
    load_stage(1);

    for (int i = 0; i < NK; i++) {
        cp_wait<1>();            // stage i landed (1 commit per iteration invariant)
        __syncthreads();
        if (i + 2 < NK) load_stage(i + 2);
        else cp_commit();        // empty group keeps wait<1> tail-correct

        int buf = i % 3;
        loadfrag(0, buf, 0);     // only this body's LDS latency is exposed
#pragma unroll
        for (int kk = 0; kk < BK / 8; kk++) {
            int cur = kk & 1;
            if (kk + 1 < BK / 8) loadfrag(cur ^ 1, buf, (kk + 1) * 8);  // hide behind MMAs
#pragma unroll
            for (int ni = 0; ni < 4; ni++)
#pragma unroll
                for (int mi = 0; mi < 2; mi++) {
                    mma_tf32(c1[mi][ni], a[cur][mi], b1f[cur][ni]);
                    mma_tf32(c3[mi][ni], a[cur][mi], b3f[cur][ni]);
                }
        }
    }

    // epilogue: SwiGLU, write fp32 h
#pragma unroll
    for (int mi = 0; mi < 2; mi++) {
#pragma unroll
        for (int hi = 0; hi < 2; hi++) {
            int row = m0 + wm * 32 + mi * 16 + g + hi * 8;
            if (row < Ne) {
                size_t base = ((size_t)e * CAP + row) * H_DIM + n0 + wn * 32;
#pragma unroll
                for (int ni = 0; ni < 4; ni++) {
                    float v1a = c1[mi][ni][hi * 2 + 0], v1b = c1[mi][ni][hi * 2 + 1];
                    float v3a = c3[mi][ni][hi * 2 + 0], v3b = c3[mi][ni][hi * 2 + 1];
                    float2 hv;
                    hv.x = (v1a / (1.f + expf(-v1a))) * v3a;
                    hv.y = (v1b / (1.f + expf(-v1b))) * v3b;
                    *(float2*)&g_h[base + ni * 8 + 2 * tg] = hv;
                }
            }
        }
    }
}

// ---------------- kernel 3: grouped GEMM  y = (h @ W2) * gate_weight ----------------
// grid (D/128, CAP/128, E_ACT), 256 threads, 128x128 tile, BK=32, same pipeline
// + fragment double-buffering.
struct P2Smem {
    float Hs[3][128][36];
    float Ws[3][BK][136];   // 136 = 8 mod 32 -> conflict-free b loads
};

__global__ __launch_bounds__(256, 2) void pass2_kernel(const float* __restrict__ w2) {
    extern __shared__ char smem_raw[];
    P2Smem* sm = (P2Smem*)smem_raw;

    int e = blockIdx.z;
    int Ne = g_counts[e];
    int m0 = blockIdx.y * 128;
    if (m0 >= Ne) return;
    int n0 = blockIdx.x * 128;

    int tid = threadIdx.x;
    int warp = tid >> 5, lane = tid & 31;
    int wm = warp >> 1, wn = warp & 1;        // warp tile 32x64
    int g = lane >> 2, tg = lane & 3;

    int xrow = tid >> 2;
    int xc4 = (tid & 3) * 4;
    const float* hg0 = g_h + ((size_t)e * CAP + m0 + xrow) * H_DIM + xc4;
    const float* hg1 = g_h + ((size_t)e * CAP + m0 + xrow + 64) * H_DIM + xc4;
    int wr = tid >> 5;
    int wc = (tid & 31) * 4;
    const float* wg = w2 + ((size_t)e * H_DIM + wr) * D_DIM + n0 + wc;

    auto load_stage = [&](int s) {
        int buf = s % 3;
        int k0 = s * BK;
        cp_async16(&sm->Hs[buf][xrow][xc4],           hg0 + k0);
        cp_async16(&sm->Hs[buf][xrow][xc4 + 16],      hg0 + k0 + 16);
        cp_async16(&sm->Hs[buf][xrow + 64][xc4],      hg1 + k0);
        cp_async16(&sm->Hs[buf][xrow + 64][xc4 + 16], hg1 + k0 + 16);
#pragma unroll
        for (int i = 0; i < 4; i++) {
            int kr = wr + 8 * i;
            cp_async16(&sm->Ws[buf][kr][wc], wg + (size_t)(k0 + 8 * i) * D_DIM);
        }
        cp_commit();
    };

    float cc[2][8][4];
#pragma unroll
    for (int mi = 0; mi < 2; mi++)
#pragma unroll
        for (int ni = 0; ni < 8; ni++)
#pragma unroll
            for (int r = 0; r < 4; r++) cc[mi][ni][r] = 0.f;

    uint32_t a[2][2][4], bf[2][8][2];
    auto loadfrag = [&](int s, int buf, int k8) {
#pragma unroll
        for (int mi = 0; mi < 2; mi++) {
            int rb = wm * 32 + mi * 16;
            a[s][mi][0] = f2tf(sm->Hs[buf][rb + g][k8 + tg]);
            a[s][mi][1] = f2tf(sm->Hs[buf][rb + g + 8][k8 + tg]);
            a[s][mi][2] = f2tf(sm->Hs[buf][rb + g][k8 + tg + 4]);
            a[s][mi][3] = f2tf(sm->Hs[buf][rb + g + 8][k8 + tg + 4]);
        }
#pragma unroll
        for (int ni = 0; ni < 8; ni++) {
            int col = wn * 64 + ni * 8 + g;
            bf[s][ni][0] = f2tf(sm->Ws[buf][k8 + tg][col]);
            bf[s][ni][1] = f2tf(sm->Ws[buf][k8 + tg + 4][col]);
        }
    };

    const int NK = H_DIM / BK;   // 176
    load_stage(0);
    load_stage(1);

    for (int i = 0; i < NK; i++) {
        cp_wait<1>();
        __syncthreads();
        if (i + 2 < NK) load_stage(i + 2);
        else cp_commit();

        int buf = i % 3;
        loadfrag(0, buf, 0);
#pragma unroll
        for (int kk = 0; kk < BK / 8; kk++) {
            int cur = kk & 1;
            if (kk + 1 < BK / 8) loadfrag(cur ^ 1, buf, (kk + 1) * 8);
#pragma unroll
            for (int ni = 0; ni < 8; ni++)
#pragma unroll
                for (int mi = 0; mi < 2; mi++)
                    mma_tf32(cc[mi][ni], a[cur][mi], bf[cur][ni]);
        }
    }

#pragma unroll
    for (int mi = 0; mi < 2; mi++) {
#pragma unroll
        for (int hi = 0; hi < 2; hi++) {
            int row = m0 + wm * 32 + mi * 16 + g + hi * 8;
            if (row < Ne) {
                float wrow = g_wgt[e * CAP + row];
                size_t base = ((size_t)e * CAP + row) * D_DIM + n0 + wn * 64;
#pragma unroll
                for (int ni = 0; ni < 8; ni++) {
                    float2 v;
                    v.x = cc[mi][ni][hi * 2 + 0] * wrow;
                    v.y = cc[mi][ni][hi * 2 + 1] * wrow;
                    *(float2*)&g_y[base + ni * 8 + 2 * tg] = v;
                }
            }
        }
    }
}

// ---------------- kernel 4: deterministic combine  out[t] = y[rowA] + y[rowB] ----------------
__global__ void combine_kernel(float* __restrict__ out) {
    int idx = blockIdx.x * blockDim.x + threadIdx.x;   // float4 index, T*D/4 total
    int t = idx >> 8;                                  // 256 float4 per token row
    int c = (idx & 255) * 4;
    int rA = g_rows[t * 2 + 0];
    int rB = g_rows[t * 2 + 1];
    float4 a = *(const float4*)&g_y[(size_t)rA * D_DIM + c];
    float4 b = *(const float4*)&g_y[(size_t)rB * D_DIM + c];
    float4 o;
    o.x = a.x + b.x; o.y = a.y + b.y; o.z = a.z + b.z; o.w = a.w + b.w;
    *(float4*)&out[(size_t)t * D_DIM + c] = o;
}

// ---------------- launch ----------------
extern "C" void kernel_launch(void* const* d_in, const int* in_sizes, int n_in,
                              void* d_out, int out_size) {
    const float* x      = (const float*)d_in[0];
    const float* gate_w = (const float*)d_in[1];
    const float* w1     = (const float*)d_in[2];
    const float* w2     = (const float*)d_in[3];
    const float* w3     = (const float*)d_in[4];
    float* out = (float*)d_out;

    cudaFuncSetAttribute(pass1_kernel, cudaFuncAttributeMaxDynamicSharedMemorySize,
                         (int)sizeof(P1Smem));
    cudaFuncSetAttribute(pass2_kernel, cudaFuncAttributeMaxDynamicSharedMemorySize,
                         (int)sizeof(P2Smem));

    zero_counts_kernel<<<1, 32>>>();
    gate_kernel<<<T_TOK / 8, 256>>>(x, gate_w);
    pass1_kernel<<<dim3(H_DIM / 64, CAP / 128, E_ACT), 256, sizeof(P1Smem)>>>(x, w1, w3);
    pass2_kernel<<<dim3(D_DIM / 128, CAP / 128, E_ACT), 256, sizeof(P2Smem)>>>(w2);
    combine_kernel<<<(T_TOK * D_DIM / 4) / 256, 256>>>(out);
}